// round 8
// baseline (speedup 1.0000x reference)
#include <cuda_runtime.h>
#include <cstdint>

// Problem constants
#define B_SZ 16
#define S_SZ 4096
#define PE_VEC 64               // float4 per pe row (256 floats)
#define TPB 256
#define ROWS_PER_TILE 8
#define TILE_F4 1024            // 8 rows * 128 float4
#define TILE_BYTES 16384
#define TILES_PER_BLOCK 8
#define N_TILES 8192            // 16*4096*512*4 / 16384
#define GRID (N_TILES / TILES_PER_BLOCK)   // 1024 blocks, 64 per batch
#define IN_STAGES 4
#define OUT_STAGES 2

// dynamic smem layout
#define SM_MBAR 0                                  // 4 x 8B mbarriers
#define SM_IN   1024
#define SM_OUT  (SM_IN + IN_STAGES * TILE_BYTES)   // 66560
#define SM_TOTAL (SM_OUT + OUT_STAGES * TILE_BYTES) // 99328

__device__ __forceinline__ uint32_t smem_u32(const void* p) {
    uint32_t a;
    asm("{ .reg .u64 t; cvta.to.shared.u64 t, %1; cvt.u32.u64 %0, t; }"
        : "=r"(a) : "l"(p));
    return a;
}
__device__ __forceinline__ void mbar_init(uint32_t mbar, uint32_t cnt) {
    asm volatile("mbarrier.init.shared.b64 [%0], %1;" :: "r"(mbar), "r"(cnt) : "memory");
}
__device__ __forceinline__ void mbar_expect_tx(uint32_t mbar, uint32_t bytes) {
    asm volatile("mbarrier.arrive.expect_tx.shared.b64 _, [%0], %1;"
                 :: "r"(mbar), "r"(bytes) : "memory");
}
__device__ __forceinline__ void mbar_wait(uint32_t mbar, uint32_t parity) {
    asm volatile(
        "{\n\t.reg .pred P;\n\t"
        "W_%=:\n\t"
        "mbarrier.try_wait.parity.acquire.cta.shared::cta.b64 P, [%0], %1, 0x989680;\n\t"
        "@!P bra W_%=;\n\t}"
        :: "r"(mbar), "r"(parity) : "memory");
}
__device__ __forceinline__ void bulk_g2s(uint32_t dst, const void* src,
                                         uint32_t bytes, uint32_t mbar) {
    asm volatile(
        "cp.async.bulk.shared::cta.global.mbarrier::complete_tx::bytes [%0], [%1], %2, [%3];"
        :: "r"(dst), "l"(src), "r"(bytes), "r"(mbar) : "memory");
}
__device__ __forceinline__ void bulk_s2g(void* dst, uint32_t src, uint32_t bytes) {
    asm volatile(
        "cp.async.bulk.global.shared::cta.bulk_group [%0], [%1], %2;"
        :: "l"(dst), "r"(src), "r"(bytes) : "memory");
}

// ---------------------------------------------------------------------------
// TMA-burst fused kernel. Per block: 8 contiguous 16KB tiles in one batch.
// 4-stage bulk-load pipeline, 2-buffer bulk-store pipeline. L computed once
// per block (overlapped with TMA prologue latency).
// ---------------------------------------------------------------------------
__global__ void __launch_bounds__(TPB) fused_pe_tma(
    const float* __restrict__ x,
    const int4*  __restrict__ mask,   // (16, 1024) int4
    const float4* __restrict__ pe,    // (5000, 64) float4
    float* __restrict__ out
) {
    extern __shared__ __align__(16) char smem[];
    const uint32_t sb  = smem_u32(smem);
    const int tid = threadIdx.x;
    const int bid = blockIdx.x;
    const int t0  = bid * TILES_PER_BLOCK;
    const int b   = bid >> 6;                 // 64 blocks per batch

    // --- init mbarriers, start 4-deep load prologue ---
    if (tid == 0) {
        #pragma unroll
        for (int i = 0; i < IN_STAGES; i++)
            mbar_init(sb + SM_MBAR + 8 * i, 1);
    }
    __syncthreads();
    if (tid == 0) {
        #pragma unroll
        for (int i = 0; i < IN_STAGES; i++) {
            const uint32_t mb = sb + SM_MBAR + 8 * i;
            mbar_expect_tx(mb, TILE_BYTES);
            bulk_g2s(sb + SM_IN + i * TILE_BYTES,
                     x + (size_t)(t0 + i) * TILE_F4 * 4, TILE_BYTES, mb);
        }
    }

    // --- L for this block's batch (overlaps TMA latency) ---
    const int4* m = mask + b * (S_SZ / 4);
    int4 mv[4];
    #pragma unroll
    for (int k = 0; k < 4; k++) mv[k] = __ldg(&m[k * TPB + tid]);
    int ones = ((mv[0].x + mv[0].y) + (mv[0].z + mv[0].w))
             + ((mv[1].x + mv[1].y) + (mv[1].z + mv[1].w))
             + ((mv[2].x + mv[2].y) + (mv[2].z + mv[2].w))
             + ((mv[3].x + mv[3].y) + (mv[3].z + mv[3].w));
    ones = __reduce_add_sync(0xFFFFFFFFu, ones);
    __shared__ __align__(16) int ws[8];
    if ((tid & 31) == 0) ws[tid >> 5] = ones;
    __syncthreads();
    const int4* wsv = reinterpret_cast<const int4*>(ws);
    const int4 w0 = wsv[0], w1 = wsv[1];
    const int L = S_SZ - (((w0.x + w0.y) + (w0.z + w0.w))
                        + ((w1.x + w1.y) + (w1.z + w1.w)));

    // --- main pipeline ---
    #pragma unroll
    for (int t = 0; t < TILES_PER_BLOCK; t++) {
        const int stage = t & 3;
        const int obuf  = t & 1;

        // out-buffer reuse: ensure store from tile t-2 has read its SMEM
        if (t >= 2) {
            if (tid == 0)
                asm volatile("cp.async.bulk.wait_group.read 1;" ::: "memory");
            __syncthreads();
        }

        mbar_wait(sb + SM_MBAR + 8 * stage, (t >> 2) & 1);

        const int tile = t0 + t;
        const int s0   = (tile & 511) * ROWS_PER_TILE;
        const float4* inb = (const float4*)(smem + SM_IN + stage * TILE_BYTES);
        float4* outb      = (float4*)(smem + SM_OUT + obuf * TILE_BYTES);

        #pragma unroll
        for (int k = 0; k < 4; k++) {
            const int j  = tid + k * TPB;        // 0..1023
            const int s  = s0 + (j >> 7);
            const int c4 = j & (PE_VEC - 1);     // (d & 255) / 4 since 64|128
            float4 v = inb[j];
            const float4 bp = pe[s * PE_VEC + c4];
            v.x += bp.x; v.y += bp.y; v.z += bp.z; v.w += bp.w;
            if (s < L) {
                const float4 rv = pe[(L - 1 - s) * PE_VEC + (PE_VEC - 1 - c4)];
                v.x += rv.w; v.y += rv.z; v.z += rv.y; v.w += rv.x;
            }
            outb[j] = v;
        }
        __syncthreads();

        if (tid == 0) {
            asm volatile("fence.proxy.async.shared::cta;" ::: "memory");
            bulk_s2g(out + (size_t)tile * TILE_F4 * 4,
                     sb + SM_OUT + obuf * TILE_BYTES, TILE_BYTES);
            asm volatile("cp.async.bulk.commit_group;" ::: "memory");
            const int tn = t + IN_STAGES;
            if (tn < TILES_PER_BLOCK) {
                const uint32_t mb = sb + SM_MBAR + 8 * stage;
                mbar_expect_tx(mb, TILE_BYTES);
                bulk_g2s(sb + SM_IN + stage * TILE_BYTES,
                         x + (size_t)(t0 + tn) * TILE_F4 * 4, TILE_BYTES, mb);
            }
        }
    }

    if (tid == 0)
        asm volatile("cp.async.bulk.wait_group 0;" ::: "memory");
}

// ---------------------------------------------------------------------------
// d_in[0] = x (f32, 16*4096*512), d_in[1] = mask (i32, 16*4096),
// d_in[2] = pe (f32, 5000*256)
// ---------------------------------------------------------------------------
extern "C" void kernel_launch(void* const* d_in, const int* in_sizes, int n_in,
                              void* d_out, int out_size) {
    const float* x    = (const float*)d_in[0];
    const int*   mask = (const int*)d_in[1];
    const float* pe   = (const float*)d_in[2];
    float* out = (float*)d_out;

    cudaFuncSetAttribute(fused_pe_tma,
                         cudaFuncAttributeMaxDynamicSharedMemorySize, SM_TOTAL);
    fused_pe_tma<<<GRID, TPB, SM_TOTAL>>>(
        x, (const int4*)mask, (const float4*)pe, out);
}

// round 9
// speedup vs baseline: 1.1601x; 1.1601x over previous
#include <cuda_runtime.h>

// Problem constants (fixed by reference setup_inputs)
#define B_SZ 16
#define S_SZ 4096
#define D_SZ 512
#define PE_DIM 256
#define VEC_PER_ROW (D_SZ / 4)       // 128 float4 per (b,s) row
#define PE_VEC_PER_ROW (PE_DIM / 4)  // 64 float4 per pe row
#define ILP 4
#define TPB 256
// block = 256 threads * ILP 4 = 1024 float4 = 8 (b,s) rows per block
// 512 blocks per batch -> b = blockIdx.x >> 9 (uniform within block)

// ---------------------------------------------------------------------------
// Fused kernel (R6 body). Single change vs R6: default write-back stores
// instead of __stcs, letting L2 (126 MB) buffer the output stream and drain
// it overlapped with the next replay's read phase.
// ---------------------------------------------------------------------------
__global__ void __launch_bounds__(TPB) fused_pe_kernel(
    const float4* __restrict__ x,
    const int4*   __restrict__ mask,  // (16, 1024) int4
    const float4* __restrict__ pe,    // (5000, 64) float4
    float4* __restrict__ out
) {
    const int tid  = threadIdx.x;
    const int base = blockIdx.x * (TPB * ILP) + tid;
    const int b    = blockIdx.x >> 9;            // 512 blocks per batch

    // 1) Mask loads first: head of the longest dependency chain
    const int4* m = mask + b * (S_SZ / 4);
    int4 mv[4];
    #pragma unroll
    for (int k = 0; k < 4; k++)
        mv[k] = __ldg(&m[k * TPB + tid]);

    // 2) Front-batch all x loads (independent, streaming, evict-first)
    float4 xv[ILP];
    #pragma unroll
    for (int k = 0; k < ILP; k++)
        xv[k] = __ldcs(&x[base + k * TPB]);

    // 3) Base-pe loads + partial sums (independent of L)
    int s_arr[ILP], c4_arr[ILP];
    float4 o[ILP];
    #pragma unroll
    for (int k = 0; k < ILP; k++) {
        const int i  = base + k * TPB;
        const int c  = i & (VEC_PER_ROW - 1);
        const int sb = i >> 7;
        s_arr[k]  = sb & (S_SZ - 1);
        c4_arr[k] = c & (PE_VEC_PER_ROW - 1);

        const float4 basev = pe[s_arr[k] * PE_VEC_PER_ROW + c4_arr[k]];
        o[k].x = xv[k].x + basev.x;
        o[k].y = xv[k].y + basev.y;
        o[k].z = xv[k].z + basev.z;
        o[k].w = xv[k].w + basev.w;
    }

    // 4) L = S - sum(mask): pure adds + REDUX + one BAR
    int ones = ((mv[0].x + mv[0].y) + (mv[0].z + mv[0].w))
             + ((mv[1].x + mv[1].y) + (mv[1].z + mv[1].w))
             + ((mv[2].x + mv[2].y) + (mv[2].z + mv[2].w))
             + ((mv[3].x + mv[3].y) + (mv[3].z + mv[3].w));
    ones = __reduce_add_sync(0xFFFFFFFFu, ones);

    __shared__ __align__(16) int warp_sums[8];   // TPB/32 = 8 warps
    if ((tid & 31) == 0) warp_sums[tid >> 5] = ones;
    __syncthreads();

    const int4* ws = reinterpret_cast<const int4*>(warp_sums);
    const int4 w0 = ws[0], w1 = ws[1];
    const int L = S_SZ - (((w0.x + w0.y) + (w0.z + w0.w))
                        + ((w1.x + w1.y) + (w1.z + w1.w)));

    // 5) Reversed-feature pe (rows L-1-s, lanes reversed)
    #pragma unroll
    for (int k = 0; k < ILP; k++) {
        if (s_arr[k] < L) {
            const int row = L - 1 - s_arr[k];    // >= 0 because s < L
            const float4 rv = pe[row * PE_VEC_PER_ROW + (PE_VEC_PER_ROW - 1 - c4_arr[k])];
            o[k].x += rv.w;
            o[k].y += rv.z;
            o[k].z += rv.y;
            o[k].w += rv.x;
        }
    }

    // 6) Default write-back stores (L2 buffers the output stream)
    #pragma unroll
    for (int k = 0; k < ILP; k++)
        out[base + k * TPB] = o[k];
}

// ---------------------------------------------------------------------------
// d_in[0] = x (f32, 16*4096*512), d_in[1] = mask (i32, 16*4096),
// d_in[2] = pe (f32, 5000*256)
// ---------------------------------------------------------------------------
extern "C" void kernel_launch(void* const* d_in, const int* in_sizes, int n_in,
                              void* d_out, int out_size) {
    const float* x    = (const float*)d_in[0];
    const int*   mask = (const int*)d_in[1];
    const float* pe   = (const float*)d_in[2];
    float* out = (float*)d_out;

    const int total_vec = B_SZ * S_SZ * VEC_PER_ROW;        // 8,388,608
    const int blocks = total_vec / (TPB * ILP);             // 8192
    fused_pe_kernel<<<blocks, TPB>>>(
        (const float4*)x, (const int4*)mask, (const float4*)pe, (float4*)out);
}